// round 3
// baseline (speedup 1.0000x reference)
#include <cuda_runtime.h>
#include <cuda_bf16.h>

#define BATCH 4
#define CDIM 128
#define CQ   16
#define NPOS 4096
#define WDIM 64

// Scratch (allocation-free rule: static __device__ arrays)
__device__ float g_q[BATCH * NPOS * CQ];    // [b][n][d]
__device__ float g_k[BATCH * CQ * NPOS];    // [b][d][n]
__device__ float g_v[BATCH * CDIM * NPOS];  // [b][c][n]

// ---------------------------------------------------------------------------
// Kernel 1: q,k projections.  grid (NPOS/32, BATCH), 256 threads
// q[b,n,d] = sum_c wq[d,c] x[b,c,n] + bq[d];  k[b,d,n] likewise
// ---------------------------------------------------------------------------
__global__ void qk_kernel(const float* __restrict__ x,
                          const float* __restrict__ wq, const float* __restrict__ bq,
                          const float* __restrict__ wk, const float* __restrict__ bk) {
    __shared__ float xs[32 * 132];     // [j][c], padded
    __shared__ float wqs[CQ * CDIM];
    __shared__ float wks[CQ * CDIM];
    const int b = blockIdx.y;
    const int n0 = blockIdx.x * 32;
    const int t = threadIdx.x;

    for (int i = t; i < CQ * CDIM; i += 256) { wqs[i] = wq[i]; wks[i] = wk[i]; }
    const float* xb = x + b * CDIM * NPOS;
    for (int i = t; i < CDIM * 32; i += 256) {
        int j = i & 31, c = i >> 5;
        xs[j * 132 + c] = xb[c * NPOS + n0 + j];   // coalesced read, transposed store
    }
    __syncthreads();

    #pragma unroll
    for (int i = 0; i < 4; i++) {
        int oidx = t + 256 * i;
        int j = oidx & 31;
        int d = (oidx >> 5) & 15;
        int mat = oidx >> 9;               // 0 = q, 1 = k
        const float* w = mat ? wks : wqs;
        const float4* wr = (const float4*)(w + d * CDIM);
        const float4* xr = (const float4*)(xs + j * 132);
        float acc = 0.f;
        #pragma unroll
        for (int c4 = 0; c4 < 32; c4++) {
            float4 a = wr[c4];
            float4 xx = xr[c4];
            acc += a.x * xx.x + a.y * xx.y + a.z * xx.z + a.w * xx.w;
        }
        int n = n0 + j;
        if (mat == 0) g_q[b * NPOS * CQ + n * CQ + d] = acc + bq[d];
        else          g_k[b * CQ * NPOS + d * NPOS + n] = acc + bk[d];
    }
}

// ---------------------------------------------------------------------------
// Kernel 2: v projection, tiled SGEMM.  grid (NPOS/128, 2, BATCH), 256 threads
// v[b,co,n] = sum_c wv[co,c] x[b,c,n] + bv[co]
// ---------------------------------------------------------------------------
__global__ void v_kernel(const float* __restrict__ x,
                         const float* __restrict__ wv, const float* __restrict__ bv) {
    __shared__ float wvs[64 * 17];      // [co][c-chunk] padded
    __shared__ float xss[16 * 132];     // [c-chunk][n] padded
    const int b = blockIdx.z;
    const int co0 = blockIdx.y * 64;
    const int n0 = blockIdx.x * 128;
    const int t = threadIdx.x;
    const int ty = t >> 5, tx = t & 31;

    float acc[8][4];
    #pragma unroll
    for (int i = 0; i < 8; i++)
        #pragma unroll
        for (int q = 0; q < 4; q++) acc[i][q] = 0.f;

    const float* xb = x + b * CDIM * NPOS;
    for (int c0 = 0; c0 < CDIM; c0 += 16) {
        __syncthreads();
        for (int i = t; i < 64 * 16; i += 256) {
            int row = i >> 4, cc = i & 15;
            wvs[row * 17 + cc] = wv[(co0 + row) * CDIM + c0 + cc];
        }
        for (int i = t; i < 512; i += 256) {
            int cr = i >> 5, j4 = i & 31;
            ((float4*)(xss + cr * 132))[j4] =
                ((const float4*)(xb + (c0 + cr) * NPOS + n0))[j4];
        }
        __syncthreads();
        #pragma unroll
        for (int cc = 0; cc < 16; cc++) {
            float a[8];
            #pragma unroll
            for (int i = 0; i < 8; i++) a[i] = wvs[(ty * 8 + i) * 17 + cc];
            float4 bb = ((const float4*)(xss + cc * 132))[tx];
            #pragma unroll
            for (int i = 0; i < 8; i++) {
                acc[i][0] += a[i] * bb.x;
                acc[i][1] += a[i] * bb.y;
                acc[i][2] += a[i] * bb.z;
                acc[i][3] += a[i] * bb.w;
            }
        }
    }
    float* vb = g_v + b * CDIM * NPOS;
    #pragma unroll
    for (int i = 0; i < 8; i++) {
        int co = co0 + ty * 8 + i;
        float bias = bv[co];
        float4 o = make_float4(acc[i][0] + bias, acc[i][1] + bias,
                               acc[i][2] + bias, acc[i][3] + bias);
        *((float4*)(vb + co * NPOS + n0 + tx * 4)) = o;
    }
}

// ---------------------------------------------------------------------------
// Kernel 3: fused attention.  grid (64, BATCH), 256 threads.
// CTA = (batch, row-block bi).  L = (bi+1)*64 valid columns.
// Thread (r = t/4, sub = t%4): row n0+r, output channels [sub*32, sub*32+32)
// ---------------------------------------------------------------------------
__global__ void att_kernel(const float* __restrict__ x,
                           const float* __restrict__ gamma_p,
                           float* __restrict__ out, float* __restrict__ att) {
    __shared__ float qs[64 * 16];
    __shared__ float ks[32 * 20];    // [j][d] padded (stride 20 -> conflict-free)
    __shared__ float vs[32 * 132];   // [j][c] padded
    __shared__ float ps[64 * 36];    // [r][j] padded (stride 36, 16B aligned)

    const int b = blockIdx.y;
    const int bi = 63 - blockIdx.x;           // largest blocks scheduled first
    const int t = threadIdx.x;
    const int r = t >> 2, sub = t & 3;
    const int n0 = bi * 64;
    const int L = (bi + 1) * 64;
    const int nch = L >> 5;

    float* attb = att + (size_t)b * NPOS * NPOS;

    // --- zero-fill masked region: cols [L, NPOS) for 64 rows ---
    const int Zf4 = (NPOS - L) >> 2;
    if (Zf4 > 0) {
        float4 z4 = make_float4(0.f, 0.f, 0.f, 0.f);
        for (int idx = t; idx < 64 * Zf4; idx += 256) {
            int row = idx / Zf4;
            int c4 = idx - row * Zf4;
            *((float4*)(attb + (size_t)(n0 + row) * NPOS + L + c4 * 4)) = z4;
        }
    }

    // --- load Q block ---
    const float* qb = g_q + b * NPOS * CQ + n0 * CQ;
    for (int i = t; i < 64 * 16; i += 256) qs[i] = qb[i];
    __syncthreads();
    float qreg[16];
    #pragma unroll
    for (int d = 0; d < 16; d++) qreg[d] = qs[r * 16 + d];

    const float* kb = g_k + b * CQ * NPOS;
    const float* vb = g_v + b * CDIM * NPOS;

    // --- Pass 1: online softmax (max & sum), each sub handles j = 4k+sub ---
    float mx = -1e30f, s = 0.f;
    for (int ch = 0; ch < nch; ch++) {
        int mc = ch * 32;
        __syncthreads();
        for (int i = t; i < 512; i += 256) {
            int d = i >> 5, j = i & 31;
            ks[j * 20 + d] = kb[d * NPOS + mc + j];
        }
        __syncthreads();
        #pragma unroll
        for (int k8 = 0; k8 < 8; k8++) {
            int j = 4 * k8 + sub;
            const float4* kr = (const float4*)(ks + j * 20);
            float e = 0.f;
            #pragma unroll
            for (int dd = 0; dd < 4; dd++) {
                float4 kk = kr[dd];
                e += qreg[dd * 4 + 0] * kk.x + qreg[dd * 4 + 1] * kk.y +
                     qreg[dd * 4 + 2] * kk.z + qreg[dd * 4 + 3] * kk.w;
            }
            if (e <= mx) {
                s += __expf(e - mx);
            } else {
                s = s * __expf(mx - e) + 1.f;
                mx = e;
            }
        }
    }
    // combine the 4 sub-threads of each row (adjacent lanes)
    #pragma unroll
    for (int d = 1; d < 4; d <<= 1) {
        float om = __shfl_xor_sync(0xffffffffu, mx, d);
        float os = __shfl_xor_sync(0xffffffffu, s, d);
        float nm = fmaxf(mx, om);
        s = s * __expf(mx - nm) + os * __expf(om - nm);
        mx = nm;
    }
    const float inv = 1.f / s;

    // --- Pass 2: recompute energy, write attention, accumulate AV ---
    float acc[32];
    #pragma unroll
    for (int i = 0; i < 32; i++) acc[i] = 0.f;

    for (int ch = 0; ch < nch; ch++) {
        int mc = ch * 32;
        __syncthreads();
        for (int i = t; i < 512; i += 256) {
            int d = i >> 5, j = i & 31;
            ks[j * 20 + d] = kb[d * NPOS + mc + j];
        }
        #pragma unroll
        for (int i = 0; i < 4; i++) {
            int idx4 = t + 256 * i;
            int c = idx4 >> 3, f4 = idx4 & 7;
            float4 vv = *((const float4*)(vb + c * NPOS + mc + f4 * 4));
            vs[(f4 * 4 + 0) * 132 + c] = vv.x;
            vs[(f4 * 4 + 1) * 132 + c] = vv.y;
            vs[(f4 * 4 + 2) * 132 + c] = vv.z;
            vs[(f4 * 4 + 3) * 132 + c] = vv.w;
        }
        __syncthreads();
        // normalized probabilities -> ps
        #pragma unroll
        for (int k8 = 0; k8 < 8; k8++) {
            int j = 4 * k8 + sub;
            const float4* kr = (const float4*)(ks + j * 20);
            float e = 0.f;
            #pragma unroll
            for (int dd = 0; dd < 4; dd++) {
                float4 kk = kr[dd];
                e += qreg[dd * 4 + 0] * kk.x + qreg[dd * 4 + 1] * kk.y +
                     qreg[dd * 4 + 2] * kk.z + qreg[dd * 4 + 3] * kk.w;
            }
            ps[r * 36 + j] = __expf(e - mx) * inv;
        }
        __syncthreads();
        // accumulate AV (sub-staggered j -> conflict-free float4 smem reads)
        #pragma unroll 4
        for (int jj = 0; jj < 32; jj++) {
            int j = (jj + sub) & 31;
            float p = ps[r * 36 + j];
            const float4* vr = (const float4*)(vs + j * 132 + sub * 32);
            #pragma unroll
            for (int c4 = 0; c4 < 8; c4++) {
                float4 vv = vr[c4];
                acc[c4 * 4 + 0] += p * vv.x;
                acc[c4 * 4 + 1] += p * vv.y;
                acc[c4 * 4 + 2] += p * vv.z;
                acc[c4 * 4 + 3] += p * vv.w;
            }
        }
        // write attention chunk (coalesced float4 from ps)
        {
            int wr = t >> 2, wc = (t & 3) * 8;
            float* dst = attb + (size_t)(n0 + wr) * NPOS + mc + wc;
            float4 p0 = *((const float4*)(ps + wr * 36 + wc));
            float4 p1 = *((const float4*)(ps + wr * 36 + wc + 4));
            ((float4*)dst)[0] = p0;
            ((float4*)dst)[1] = p1;
        }
    }

    // --- epilogue: out = gamma*acc + x ---
    const float g = *gamma_p;
    const int n = n0 + r;
    const float* xb = x + b * CDIM * NPOS;
    float* ob = out + b * CDIM * NPOS;
    #pragma unroll
    for (int i = 0; i < 32; i++) {
        int c = sub * 32 + i;
        ob[c * NPOS + n] = g * acc[i] + xb[c * NPOS + n];
    }
}

// ---------------------------------------------------------------------------
extern "C" void kernel_launch(void* const* d_in, const int* in_sizes, int n_in,
                              void* d_out, int out_size) {
    const float* x     = (const float*)d_in[0];
    const float* wq    = (const float*)d_in[1];
    const float* bq    = (const float*)d_in[2];
    const float* wk    = (const float*)d_in[3];
    const float* bk    = (const float*)d_in[4];
    const float* wv    = (const float*)d_in[5];
    const float* bv    = (const float*)d_in[6];
    const float* gamma = (const float*)d_in[7];

    float* out = (float*)d_out;
    float* att = out + BATCH * CDIM * NPOS;   // tuple: (out, attention)

    qk_kernel<<<dim3(NPOS / 32, BATCH), 256>>>(x, wq, bq, wk, bk);
    v_kernel<<<dim3(NPOS / 128, 2, BATCH), 256>>>(x, wv, bv);
    att_kernel<<<dim3(64, BATCH), 256>>>(x, gamma, out, att);
}

// round 8
// speedup vs baseline: 4.9096x; 4.9096x over previous
#include <cuda_runtime.h>
#include <cstdint>
#include <cstddef>

#define BATCH 4
#define CDIM 128
#define CQ   16
#define NPOS 4096

// Scratch (allocation-free rule)
__device__ float g_q[BATCH * NPOS * CQ];    // [b][n][d]
__device__ float g_k[BATCH * NPOS * CQ];    // [b][n][d]
__device__ float g_v[BATCH * CDIM * NPOS];  // [b][c][n]

// ============================ mma.sync helpers (sm_80+ PTX, no 'a' features) ============================
__device__ __forceinline__ void mma_tf32(float* d, const uint32_t* a, uint32_t b0, uint32_t b1) {
    asm volatile("mma.sync.aligned.m16n8k8.row.col.f32.tf32.tf32.f32 "
        "{%0,%1,%2,%3}, {%4,%5,%6,%7}, {%8,%9}, {%0,%1,%2,%3};"
        : "+f"(d[0]), "+f"(d[1]), "+f"(d[2]), "+f"(d[3])
        : "r"(a[0]), "r"(a[1]), "r"(a[2]), "r"(a[3]), "r"(b0), "r"(b1));
}
__device__ __forceinline__ uint32_t f2tf(float f) {
    uint32_t u; asm("cvt.rna.tf32.f32 %0, %1;" : "=r"(u) : "f"(f)); return u;
}

// ============================ Kernel 1: q,k projection ============================
__global__ void __launch_bounds__(256) qk_kernel(
        const float* __restrict__ x,
        const float* __restrict__ wq, const float* __restrict__ bq,
        const float* __restrict__ wk, const float* __restrict__ bk) {
    __shared__ float wqs[CQ * CDIM];
    __shared__ float wks[CQ * CDIM];
    __shared__ float xs[32 * 132];
    const int b = blockIdx.y;
    const int n0 = blockIdx.x * 32;
    const int t = threadIdx.x;

    for (int i = t; i < CQ * CDIM; i += 256) { wqs[i] = wq[i]; wks[i] = wk[i]; }
    const float* xb = x + b * CDIM * NPOS;
    for (int i = t; i < CDIM * 32; i += 256) {
        int j = i & 31, c = i >> 5;
        xs[j * 132 + c] = xb[c * NPOS + n0 + j];
    }
    __syncthreads();

    #pragma unroll 1
    for (int i = 0; i < 4; i++) {
        int oidx = t + 256 * i;
        int j = oidx & 31;
        int d = (oidx >> 5) & 15;
        int mat = oidx >> 9;
        const float* w = mat ? wks : wqs;
        const float4* wr = (const float4*)(w + d * CDIM);
        const float4* xr = (const float4*)(xs + j * 132);
        float acc = 0.f;
        #pragma unroll 8
        for (int c4 = 0; c4 < 32; c4++) {
            float4 a = wr[c4];
            float4 xx = xr[c4];
            acc += a.x * xx.x + a.y * xx.y + a.z * xx.z + a.w * xx.w;
        }
        int n = n0 + j;
        if (mat == 0) g_q[(b * NPOS + n) * CQ + d] = acc + bq[d];
        else          g_k[(b * NPOS + n) * CQ + d] = acc + bk[d];
    }
}

// ============================ Kernel 2: v projection ============================
__global__ void __launch_bounds__(256) v_kernel(
        const float* __restrict__ x,
        const float* __restrict__ wv, const float* __restrict__ bv) {
    __shared__ float wvs[64 * 17];
    __shared__ float xss[16 * 132];
    const int b = blockIdx.z;
    const int co0 = blockIdx.y * 64;
    const int n0 = blockIdx.x * 128;
    const int t = threadIdx.x;
    const int ty = t >> 5, tx = t & 31;

    float acc[8][4];
    #pragma unroll
    for (int i = 0; i < 8; i++)
        #pragma unroll
        for (int q = 0; q < 4; q++) acc[i][q] = 0.f;

    const float* xb = x + b * CDIM * NPOS;
    for (int c0 = 0; c0 < CDIM; c0 += 16) {
        __syncthreads();
        for (int i = t; i < 64 * 16; i += 256) {
            int row = i >> 4, cc = i & 15;
            wvs[row * 17 + cc] = wv[(co0 + row) * CDIM + c0 + cc];
        }
        for (int i = t; i < 512; i += 256) {
            int cr = i >> 5, j4 = i & 31;
            ((float4*)(xss + cr * 132))[j4] =
                ((const float4*)(xb + (c0 + cr) * NPOS + n0))[j4];
        }
        __syncthreads();
        #pragma unroll
        for (int cc = 0; cc < 16; cc++) {
            float a[8];
            #pragma unroll
            for (int i = 0; i < 8; i++) a[i] = wvs[(ty * 8 + i) * 17 + cc];
            float4 bb = ((const float4*)(xss + cc * 132))[tx];
            #pragma unroll
            for (int i = 0; i < 8; i++) {
                acc[i][0] += a[i] * bb.x;
                acc[i][1] += a[i] * bb.y;
                acc[i][2] += a[i] * bb.z;
                acc[i][3] += a[i] * bb.w;
            }
        }
    }
    float* vb = g_v + b * CDIM * NPOS;
    #pragma unroll
    for (int i = 0; i < 8; i++) {
        int co = co0 + ty * 8 + i;
        float bias = bv[co];
        float4 o = make_float4(acc[i][0] + bias, acc[i][1] + bias,
                               acc[i][2] + bias, acc[i][3] + bias);
        *((float4*)(vb + co * NPOS + n0 + tx * 4)) = o;
    }
}

// ============================ Kernel 3: mma.sync attention ============================
// CTA = (b, pair pr): processes row-block pr then row-block 63-pr (64 rows each).
// Row-block blk: rows n0=blk*64.., valid cols L=(blk+1)*64 (chunk-aligned -> no partial mask).
// Total chunks per CTA = (pr+1) + (64-pr) = 65 for every CTA (balanced).
//
// 256 threads = 8 warps; warp w: mg=w&1 (rows mg*32..+31 as 2 m16-tiles),
//                               ng=w>>1 (S: n-tiles 2ng..2ng+1; AV: c-tiles 4ng..4ng+3).
// SMEM float offsets:
#define SQ_OFF   0                  // Q hi/lo: 64 rows x 36
#define SK_OFF   2304               // K hi/lo: 64 rows x 36
#define SV_OFF   4608               // V: 128 c x 68  (also O staging in epilogue)
#define SP_OFF   13312              // P: 64 rows x 72
#define SZ_OFF   17920              // zred: 8 x 32
#define SI_OFF   18176              // inv: 64
#define SM_FLOATS 18240
#define SM_BYTES (SM_FLOATS * 4)

__global__ void __launch_bounds__(256, 1) att_kernel(
        const float* __restrict__ x, const float* __restrict__ gamma_p,
        float* __restrict__ out, float* __restrict__ att) {
    extern __shared__ float sm[];
    float* qb_s = sm + SQ_OFF;
    float* kb_s = sm + SK_OFF;
    float* vb_s = sm + SV_OFF;
    float* pb_s = sm + SP_OFF;
    float* zr_s = sm + SZ_OFF;
    float* in_s = sm + SI_OFF;
    const uint32_t* kbu = (const uint32_t*)kb_s;
    const uint32_t* vbu = (const uint32_t*)vb_s;
    const uint32_t* pbu = (const uint32_t*)pb_s;
    const uint32_t* qbu = (const uint32_t*)qb_s;

    const int b = blockIdx.y;
    const int pr = blockIdx.x;
    const int tid = threadIdx.x;
    const int w = tid >> 5, lane = tid & 31;
    const int g = lane >> 2, tig = lane & 3;
    const int mg = w & 1, ng = w >> 1;
    const float gam = *gamma_p;

    const float* qg = g_q + (size_t)b * NPOS * CQ;
    const float* kg = g_k + (size_t)b * NPOS * CQ;
    const float* vg = g_v + (size_t)b * CDIM * NPOS;
    float* attb = att + (size_t)b * NPOS * NPOS;
    const float* xb = x + (size_t)b * CDIM * NPOS;
    float* ob = out + (size_t)b * CDIM * NPOS;

    #pragma unroll 1
    for (int ph = 0; ph < 2; ph++) {
        const int blk = ph ? (63 - pr) : pr;
        const int n0 = blk * 64;
        const int nch = blk + 1;
        const int L = n0 + 64;

        // ---- zero-fill masked attention cols [L, 4096) for these 64 rows ----
        {
            const int nz4 = (NPOS - L) >> 2;
            float4 z = make_float4(0.f, 0.f, 0.f, 0.f);
            for (int idx = tid; idx < 64 * nz4; idx += 256) {
                int r = idx / nz4, c4 = idx - r * nz4;
                *((float4*)(attb + (size_t)(n0 + r) * NPOS + L + c4 * 4)) = z;
            }
        }

        // ---- load Q block (hi/lo split) ----
        __syncthreads();   // smem reuse vs previous phase
        {
            int r = tid >> 2, f = tid & 3;
            float4 v = *((const float4*)(qg + (size_t)(n0 + r) * CQ + f * 4));
            float4 hi, lo;
            hi.x = __uint_as_float(__float_as_uint(v.x) & 0xFFFFE000u); lo.x = v.x - hi.x;
            hi.y = __uint_as_float(__float_as_uint(v.y) & 0xFFFFE000u); lo.y = v.y - hi.y;
            hi.z = __uint_as_float(__float_as_uint(v.z) & 0xFFFFE000u); lo.z = v.z - hi.z;
            hi.w = __uint_as_float(__float_as_uint(v.w) & 0xFFFFE000u); lo.w = v.w - hi.w;
            *((float4*)(qb_s + r * 36 + f * 4)) = hi;
            *((float4*)(qb_s + r * 36 + 16 + f * 4)) = lo;
        }
        __syncthreads();

        // ---- Q fragments (constant per phase): [mtl][set hi0,hi1,lo0,lo1][4] ----
        uint32_t qf[2][4][4];
        #pragma unroll
        for (int mtl = 0; mtl < 2; mtl++) {
            int r0 = (mg * 32 + mtl * 16 + g) * 36;
            int r1 = r0 + 8 * 36;
            #pragma unroll
            for (int s = 0; s < 4; s++) {        // d-offset: 0, 8, 16, 24
                int off = s * 8;
                qf[mtl][s][0] = qbu[r0 + off + tig];
                qf[mtl][s][1] = qbu[r1 + off + tig];
                qf[mtl][s][2] = qbu[r0 + off + tig + 4];
                qf[mtl][s][3] = qbu[r1 + off + tig + 4];
            }
        }

        // ================= Pass 1: row sums of exp(S) =================
        float z[2][2] = {{0.f, 0.f}, {0.f, 0.f}};
        #pragma unroll 1
        for (int ch = 0; ch < nch; ch++) {
            const int mc = ch * 64;
            __syncthreads();
            {
                int r = tid >> 2, f = tid & 3;
                float4 v = *((const float4*)(kg + (size_t)(mc + r) * CQ + f * 4));
                float4 hi, lo;
                hi.x = __uint_as_float(__float_as_uint(v.x) & 0xFFFFE000u); lo.x = v.x - hi.x;
                hi.y = __uint_as_float(__float_as_uint(v.y) & 0xFFFFE000u); lo.y = v.y - hi.y;
                hi.z = __uint_as_float(__float_as_uint(v.z) & 0xFFFFE000u); lo.z = v.z - hi.z;
                hi.w = __uint_as_float(__float_as_uint(v.w) & 0xFFFFE000u); lo.w = v.w - hi.w;
                *((float4*)(kb_s + r * 36 + f * 4)) = hi;
                *((float4*)(kb_s + r * 36 + 16 + f * 4)) = lo;
            }
            __syncthreads();
            #pragma unroll
            for (int mtl = 0; mtl < 2; mtl++) {
                #pragma unroll
                for (int ntl = 0; ntl < 2; ntl++) {
                    const int nt = ng * 2 + ntl;
                    const int kr = (nt * 8 + g) * 36;
                    uint32_t kh0a = kbu[kr + tig],      kh0b = kbu[kr + tig + 4];
                    uint32_t kh1a = kbu[kr + 8 + tig],  kh1b = kbu[kr + 8 + tig + 4];
                    uint32_t kl0a = kbu[kr + 16 + tig], kl0b = kbu[kr + 16 + tig + 4];
                    uint32_t kl1a = kbu[kr + 24 + tig], kl1b = kbu[kr + 24 + tig + 4];
                    float d[4] = {0.f, 0.f, 0.f, 0.f};
                    mma_tf32(d, qf[mtl][0], kh0a, kh0b);
                    mma_tf32(d, qf[mtl][1], kh1a, kh1b);
                    mma_tf32(d, qf[mtl][0], kl0a, kl0b);
                    mma_tf32(d, qf[mtl][1], kl1a, kl1b);
                    mma_tf32(d, qf[mtl][2], kh0a, kh0b);
                    mma_tf32(d, qf[mtl][3], kh1a, kh1b);
                    z[mtl][0] += __expf(d[0]) + __expf(d[1]);
                    z[mtl][1] += __expf(d[2]) + __expf(d[3]);
                }
            }
        }
        // reduce over tig lanes
        #pragma unroll
        for (int off = 1; off < 4; off <<= 1) {
            #pragma unroll
            for (int mtl = 0; mtl < 2; mtl++) {
                z[mtl][0] += __shfl_xor_sync(0xffffffffu, z[mtl][0], off);
                z[mtl][1] += __shfl_xor_sync(0xffffffffu, z[mtl][1], off);
            }
        }
        __syncthreads();   // zr_s reuse vs previous phase
        if (tig == 0) {
            zr_s[w * 32 + mg * 0 + 0 * 16 + g]      = z[0][0];  // row mtl0, g
            zr_s[w * 32 + 0 * 16 + g + 8]           = z[0][1];
            zr_s[w * 32 + 16 + g]                   = z[1][0];
            zr_s[w * 32 + 16 + g + 8]               = z[1][1];
        }
        __syncthreads();
        if (tid < 64) {
            int r = tid;
            int mgr = r >> 5, lr = r & 31;
            float s = zr_s[(mgr + 0) * 32 + lr] + zr_s[(mgr + 2) * 32 + lr] +
                      zr_s[(mgr + 4) * 32 + lr] + zr_s[(mgr + 6) * 32 + lr];
            in_s[r] = 1.f / s;
        }
        __syncthreads();
        float myinv[2][2];
        #pragma unroll
        for (int mtl = 0; mtl < 2; mtl++) {
            myinv[mtl][0] = in_s[mg * 32 + mtl * 16 + g];
            myinv[mtl][1] = in_s[mg * 32 + mtl * 16 + g + 8];
        }

        // ================= Pass 2: P + O = P*V =================
        float o[2][4][4];
        #pragma unroll
        for (int i = 0; i < 2; i++)
            #pragma unroll
            for (int j = 0; j < 4; j++)
                #pragma unroll
                for (int k = 0; k < 4; k++) o[i][j][k] = 0.f;

        #pragma unroll 1
        for (int ch = 0; ch < nch; ch++) {
            const int mc = ch * 64;
            __syncthreads();
            {   // K chunk (hi/lo)
                int r = tid >> 2, f = tid & 3;
                float4 v = *((const float4*)(kg + (size_t)(mc + r) * CQ + f * 4));
                float4 hi, lo;
                hi.x = __uint_as_float(__float_as_uint(v.x) & 0xFFFFE000u); lo.x = v.x - hi.x;
                hi.y = __uint_as_float(__float_as_uint(v.y) & 0xFFFFE000u); lo.y = v.y - hi.y;
                hi.z = __uint_as_float(__float_as_uint(v.z) & 0xFFFFE000u); lo.z = v.z - hi.z;
                hi.w = __uint_as_float(__float_as_uint(v.w) & 0xFFFFE000u); lo.w = v.w - hi.w;
                *((float4*)(kb_s + r * 36 + f * 4)) = hi;
                *((float4*)(kb_s + r * 36 + 16 + f * 4)) = lo;
            }
            // V chunk: vb_s[c][m], tf32-rounded
            #pragma unroll
            for (int it = 0; it < 8; it++) {
                int idx = tid + 256 * it;
                int c = idx >> 4, f4 = idx & 15;
                float4 v = *((const float4*)(vg + (size_t)c * NPOS + mc + f4 * 4));
                uint4 u = make_uint4(f2tf(v.x), f2tf(v.y), f2tf(v.z), f2tf(v.w));
                *((uint4*)(vb_s + c * 68 + f4 * 4)) = u;
            }
            __syncthreads();
            // S, exp, normalized P -> pb_s
            #pragma unroll
            for (int mtl = 0; mtl < 2; mtl++) {
                #pragma unroll
                for (int ntl = 0; ntl < 2; ntl++) {
                    const int nt = ng * 2 + ntl;
                    const int kr = (nt * 8 + g) * 36;
                    uint32_t kh0a = kbu[kr + tig],      kh0b = kbu[kr + tig + 4];
                    uint32_t kh1a = kbu[kr + 8 + tig],  kh1b = kbu[kr + 8 + tig + 4];
                    uint32_t kl0a = kbu[kr + 16 + tig], kl0b = kbu[kr + 16 + tig + 4];
                    uint32_t kl1a = kbu[kr + 24 + tig], kl1b = kbu[kr + 24 + tig + 4];
                    float d[4] = {0.f, 0.f, 0.f, 0.f};
                    mma_tf32(d, qf[mtl][0], kh0a, kh0b);
                    mma_tf32(d, qf[mtl][1], kh1a, kh1b);
                    mma_tf32(d, qf[mtl][0], kl0a, kl0b);
                    mma_tf32(d, qf[mtl][1], kl1a, kl1b);
                    mma_tf32(d, qf[mtl][2], kh0a, kh0b);
                    mma_tf32(d, qf[mtl][3], kh1a, kh1b);
                    int r0 = mg * 32 + mtl * 16 + g;
                    float2 p0 = make_float2(__expf(d[0]) * myinv[mtl][0],
                                            __expf(d[1]) * myinv[mtl][0]);
                    float2 p1 = make_float2(__expf(d[2]) * myinv[mtl][1],
                                            __expf(d[3]) * myinv[mtl][1]);
                    *((float2*)(pb_s + r0 * 72 + nt * 8 + 2 * tig)) = p0;
                    *((float2*)(pb_s + (r0 + 8) * 72 + nt * 8 + 2 * tig)) = p1;
                }
            }
            __syncthreads();
            // AV: O += P * V
            #pragma unroll
            for (int ks = 0; ks < 8; ks++) {
                uint32_t af[2][4];
                #pragma unroll
                for (int mtl = 0; mtl < 2; mtl++) {
                    int r0 = (mg * 32 + mtl * 16 + g) * 72 + ks * 8;
                    int r1 = r0 + 8 * 72;
                    af[mtl][0] = pbu[r0 + tig];
                    af[mtl][1] = pbu[r1 + tig];
                    af[mtl][2] = pbu[r0 + tig + 4];
                    af[mtl][3] = pbu[r1 + tig + 4];
                }
                #pragma unroll
                for (int cnt = 0; cnt < 4; cnt++) {
                    int cr = ((ng * 4 + cnt) * 8 + g) * 68 + ks * 8;
                    uint32_t b0 = vbu[cr + tig], b1 = vbu[cr + tig + 4];
                    mma_tf32(o[0][cnt], af[0], b0, b1);
                    mma_tf32(o[1][cnt], af[1], b0, b1);
                }
            }
            // attention gmem write (coalesced from pb_s)
            #pragma unroll
            for (int it = 0; it < 4; it++) {
                int idx = tid + 256 * it;
                int r = idx >> 4, f4 = idx & 15;
                float4 p4 = *((const float4*)(pb_s + r * 72 + f4 * 4));
                *((float4*)(attb + (size_t)(n0 + r) * NPOS + mc + f4 * 4)) = p4;
            }
        }

        // ================= Epilogue: out = gamma*O + x =================
        __syncthreads();   // all warps done reading vb_s
        #pragma unroll
        for (int mtl = 0; mtl < 2; mtl++) {
            int r0 = mg * 32 + mtl * 16 + g;
            #pragma unroll
            for (int cnt = 0; cnt < 4; cnt++) {
                int c0 = (ng * 4 + cnt) * 8 + 2 * tig;
                vb_s[c0 * 68 + r0]           = o[mtl][cnt][0];
                vb_s[(c0 + 1) * 68 + r0]     = o[mtl][cnt][1];
                vb_s[c0 * 68 + r0 + 8]       = o[mtl][cnt][2];
                vb_s[(c0 + 1) * 68 + r0 + 8] = o[mtl][cnt][3];
            }
        }
        __syncthreads();
        #pragma unroll
        for (int it = 0; it < 8; it++) {
            int idx = tid + 256 * it;
            int c = idx >> 4, f4 = idx & 15;
            float4 ov = *((const float4*)(vb_s + c * 68 + f4 * 4));
            const float* xp = xb + (size_t)c * NPOS + n0 + f4 * 4;
            float4 xv = *((const float4*)xp);
            float4 res = make_float4(gam * ov.x + xv.x, gam * ov.y + xv.y,
                                     gam * ov.z + xv.z, gam * ov.w + xv.w);
            *((float4*)(ob + (size_t)c * NPOS + n0 + f4 * 4)) = res;
        }
    }
}

// ---------------------------------------------------------------------------
extern "C" void kernel_launch(void* const* d_in, const int* in_sizes, int n_in,
                              void* d_out, int out_size) {
    const float* x     = (const float*)d_in[0];
    const float* wq    = (const float*)d_in[1];
    const float* bq    = (const float*)d_in[2];
    const float* wk    = (const float*)d_in[3];
    const float* bk    = (const float*)d_in[4];
    const float* wv    = (const float*)d_in[5];
    const float* bv    = (const float*)d_in[6];
    const float* gamma = (const float*)d_in[7];

    float* out = (float*)d_out;
    float* att = out + BATCH * CDIM * NPOS;

    static bool attr_set = false;
    if (!attr_set) {
        cudaFuncSetAttribute(att_kernel, cudaFuncAttributeMaxDynamicSharedMemorySize, SM_BYTES);
        attr_set = true;
    }

    qk_kernel<<<dim3(NPOS / 32, BATCH), 256>>>(x, wq, bq, wk, bk);
    v_kernel<<<dim3(NPOS / 128, 2, BATCH), 256>>>(x, wv, bv);
    att_kernel<<<dim3(32, BATCH), 256, SM_BYTES>>>(x, gamma, out, att);
}